// round 1
// baseline (speedup 1.0000x reference)
#include <cuda_runtime.h>
#include <cuda_bf16.h>
#include <cstdint>

// ---------------- constants ----------------
#define TEMP_INV 10.0f          // 1 / 0.1
#define TILE_M   128            // edges per CTA
#define PA       264            // A tile pitch (bf16 elems), pad to dodge bank conflicts
#define PW       136            // W1 chunk pitch (bf16)
#define PH       136            // H tile pitch (bf16)
#define PW2      72             // W2 pitch (bf16)
#define PO       68             // OUT pitch (fp32)

#define OFF_W    67584          // zone1 offset: after sA (128*264*2)
#define OFF_IDX  86016          // zone2 offset: OFF_W + max(8704, 18432)
#define SMEM_TOTAL 87072        // OFF_IDX + 1024 (idx) + 32 (warp sums)

__device__ float g_partials[8192];

// ---------------- PTX helpers ----------------
__device__ __forceinline__ uint32_t sptr(const void* p) {
    return (uint32_t)__cvta_generic_to_shared(p);
}

__device__ __forceinline__ void ldm_x4(uint32_t a, uint32_t& r0, uint32_t& r1,
                                       uint32_t& r2, uint32_t& r3) {
    asm volatile("ldmatrix.sync.aligned.m8n8.x4.shared.b16 {%0,%1,%2,%3}, [%4];"
                 : "=r"(r0), "=r"(r1), "=r"(r2), "=r"(r3) : "r"(a));
}

__device__ __forceinline__ void ldm_x4_t(uint32_t a, uint32_t& r0, uint32_t& r1,
                                         uint32_t& r2, uint32_t& r3) {
    asm volatile("ldmatrix.sync.aligned.m8n8.x4.trans.shared.b16 {%0,%1,%2,%3}, [%4];"
                 : "=r"(r0), "=r"(r1), "=r"(r2), "=r"(r3) : "r"(a));
}

__device__ __forceinline__ void mma16816(float* d, const uint32_t* a,
                                         uint32_t b0, uint32_t b1) {
    asm volatile(
        "mma.sync.aligned.m16n8k16.row.col.f32.bf16.bf16.f32 "
        "{%0,%1,%2,%3}, {%4,%5,%6,%7}, {%8,%9}, {%0,%1,%2,%3};"
        : "+f"(d[0]), "+f"(d[1]), "+f"(d[2]), "+f"(d[3])
        : "r"(a[0]), "r"(a[1]), "r"(a[2]), "r"(a[3]), "r"(b0), "r"(b1));
}

__device__ __forceinline__ float warp_sum(float v) {
    v += __shfl_xor_sync(0xffffffffu, v, 16);
    v += __shfl_xor_sync(0xffffffffu, v, 8);
    v += __shfl_xor_sync(0xffffffffu, v, 4);
    v += __shfl_xor_sync(0xffffffffu, v, 2);
    v += __shfl_xor_sync(0xffffffffu, v, 1);
    return v;
}

// ---------------- fused kernel ----------------
// Phases per CTA (128 edges):
//  1. gather [u|i] rows -> sA bf16 [128,256]
//  2. GEMM1: H = relu(A @ W1)  (W1 streamed in K=32 chunks from L2)
//  3. GEMM2: OUT = H @ W2
//  4. epilogue: paired InfoNCE per edge, block partial -> g_partials
__global__ void __launch_bounds__(256, 2) fused_kernel(
    const float* __restrict__ ufeat, const float* __restrict__ ifeat,
    const float* __restrict__ review, const float* __restrict__ negs,
    const float* __restrict__ W1, const float* __restrict__ W2,
    const int* __restrict__ src, const int* __restrict__ dst, int E)
{
    extern __shared__ char smem[];
    __nv_bfloat16* sA = (__nv_bfloat16*)smem;                 // zone0
    __nv_bfloat16* sW = (__nv_bfloat16*)(smem + OFF_W);       // zone1
    int* sSrc = (int*)(smem + OFF_IDX);
    int* sDst = sSrc + 128;
    float* wSums = (float*)(smem + OFF_IDX + 1024);

    const int tid = threadIdx.x;
    const int lane = tid & 31;
    const int wid = tid >> 5;
    const int base = blockIdx.x * TILE_M;

    // ---- preload indices (clamp tail to a valid row; unused rows are skipped) ----
    if (tid < 128) {
        int e = base + tid;
        sSrc[tid] = (e < E) ? src[e] : src[0];
    } else {
        int t = tid - 128;
        int e = base + t;
        sDst[t] = (e < E) ? dst[e] : dst[0];
    }
    __syncthreads();

    // ---- phase 1: gather A tile (concat u|i), fp32 -> bf16 ----
    #pragma unroll 4
    for (int i = tid; i < 128 * 64; i += 256) {
        int r = i >> 6;
        int c = (i & 63) * 4;       // float column, multiple of 4
        const float* p = (c < 128) ? (ufeat + (size_t)sSrc[r] * 128 + c)
                                   : (ifeat + (size_t)sDst[r] * 128 + (c - 128));
        float4 v = *(const float4*)p;
        __nv_bfloat162* d = (__nv_bfloat162*)&sA[r * PA + c];
        d[0] = __floats2bfloat162_rn(v.x, v.y);
        d[1] = __floats2bfloat162_rn(v.z, v.w);
    }

    // ---- phase 2: GEMM1  C[128,128] = A[128,256] @ W1[256,128] ----
    float acc[2][8][4];
    #pragma unroll
    for (int a = 0; a < 2; ++a)
        #pragma unroll
        for (int b = 0; b < 8; ++b)
            #pragma unroll
            for (int c = 0; c < 4; ++c) acc[a][b][c] = 0.f;

    const int wm = (wid & 3) * 32;   // warp M offset (4 warps over M)
    const int wn = (wid >> 2) * 64;  // warp N offset (2 warps over N)

    for (int kc = 0; kc < 8; ++kc) {
        __syncthreads();  // prior chunk mma reads done (iter0: no-op ordering)
        // stage W1 rows [kc*32, kc*32+32) as bf16
        #pragma unroll
        for (int i = tid; i < 32 * 32; i += 256) {
            int r = i >> 5;
            int c = (i & 31) * 4;
            float4 v = *(const float4*)(W1 + (size_t)(kc * 32 + r) * 128 + c);
            __nv_bfloat162* d = (__nv_bfloat162*)&sW[r * PW + c];
            d[0] = __floats2bfloat162_rn(v.x, v.y);
            d[1] = __floats2bfloat162_rn(v.z, v.w);
        }
        __syncthreads();  // also guarantees gather of sA complete (first iter)

        #pragma unroll
        for (int ks = 0; ks < 2; ++ks) {
            int kg = kc * 32 + ks * 16;
            uint32_t a0[4], a1[4];
            ldm_x4(sptr(&sA[(wm + (lane & 15)) * PA + kg + ((lane >> 4) << 3)]),
                   a0[0], a0[1], a0[2], a0[3]);
            ldm_x4(sptr(&sA[(wm + 16 + (lane & 15)) * PA + kg + ((lane >> 4) << 3)]),
                   a1[0], a1[1], a1[2], a1[3]);
            #pragma unroll
            for (int nb = 0; nb < 4; ++nb) {
                uint32_t b0, b1, b2, b3;
                ldm_x4_t(sptr(&sW[(ks * 16 + (lane & 15)) * PW + wn + nb * 16 +
                                  ((lane >> 4) << 3)]),
                         b0, b1, b2, b3);
                mma16816(acc[0][2 * nb],     a0, b0, b1);
                mma16816(acc[0][2 * nb + 1], a0, b2, b3);
                mma16816(acc[1][2 * nb],     a1, b0, b1);
                mma16816(acc[1][2 * nb + 1], a1, b2, b3);
            }
        }
    }
    __syncthreads();  // all GEMM1 smem reads done before overwriting zones

    // ---- relu + store H (bf16, overwrites sA zone) ; stage W2 (overwrites sW) ----
    __nv_bfloat16* sH = (__nv_bfloat16*)smem;
    #pragma unroll
    for (int mi = 0; mi < 2; ++mi)
        #pragma unroll
        for (int nj = 0; nj < 8; ++nj) {
            int row = wm + mi * 16 + (lane >> 2);
            int col = wn + nj * 8 + (lane & 3) * 2;
            float* c = acc[mi][nj];
            *(__nv_bfloat162*)&sH[row * PH + col] =
                __floats2bfloat162_rn(fmaxf(c[0], 0.f), fmaxf(c[1], 0.f));
            *(__nv_bfloat162*)&sH[(row + 8) * PH + col] =
                __floats2bfloat162_rn(fmaxf(c[2], 0.f), fmaxf(c[3], 0.f));
        }

    __nv_bfloat16* sW2 = (__nv_bfloat16*)(smem + OFF_W);
    #pragma unroll
    for (int i = tid; i < 128 * 16; i += 256) {
        int r = i >> 4;
        int c = (i & 15) * 4;
        float4 v = *(const float4*)(W2 + (size_t)r * 64 + c);
        __nv_bfloat162* d = (__nv_bfloat162*)&sW2[r * PW2 + c];
        d[0] = __floats2bfloat162_rn(v.x, v.y);
        d[1] = __floats2bfloat162_rn(v.z, v.w);
    }
    __syncthreads();

    // ---- phase 3: GEMM2  OUT[128,64] = H[128,128] @ W2[128,64] ----
    float acc2[8][4];
    #pragma unroll
    for (int b = 0; b < 8; ++b)
        #pragma unroll
        for (int c = 0; c < 4; ++c) acc2[b][c] = 0.f;

    const int m0 = wid * 16;  // 8 warps over M, each warp does 16x64
    #pragma unroll
    for (int k = 0; k < 8; ++k) {
        int kg = k * 16;
        uint32_t a[4];
        ldm_x4(sptr(&sH[(m0 + (lane & 15)) * PH + kg + ((lane >> 4) << 3)]),
               a[0], a[1], a[2], a[3]);
        #pragma unroll
        for (int nb = 0; nb < 4; ++nb) {
            uint32_t b0, b1, b2, b3;
            ldm_x4_t(sptr(&sW2[(kg + (lane & 15)) * PW2 + nb * 16 +
                               ((lane >> 4) << 3)]),
                     b0, b1, b2, b3);
            mma16816(acc2[2 * nb],     a, b0, b1);
            mma16816(acc2[2 * nb + 1], a, b2, b3);
        }
    }
    __syncthreads();  // all H reads done before OUT overwrites zone0

    float* sOUT = (float*)smem;
    #pragma unroll
    for (int nj = 0; nj < 8; ++nj) {
        int row = m0 + (lane >> 2);
        int col = nj * 8 + (lane & 3) * 2;
        *(float2*)&sOUT[row * PO + col]       = make_float2(acc2[nj][0], acc2[nj][1]);
        *(float2*)&sOUT[(row + 8) * PO + col] = make_float2(acc2[nj][2], acc2[nj][3]);
    }
    __syncthreads();

    // ---- phase 4: paired InfoNCE epilogue (warp handles 16 edges) ----
    float lsum = 0.f;
    for (int rr = 0; rr < 16; ++rr) {
        int r = m0 + rr;
        int e = base + r;          // warp-uniform
        if (e >= E) continue;

        float o0 = sOUT[r * PO + lane];
        float o1 = sOUT[r * PO + 32 + lane];
        float rq = rsqrtf(warp_sum(o0 * o0 + o1 * o1));

        const float* pr = review + (size_t)e * 64;
        float p0 = pr[lane], p1 = pr[lane + 32];
        float dp = warp_sum(o0 * p0 + o1 * p1);
        float np = warp_sum(p0 * p0 + p1 * p1);
        float pos = dp * rq * rsqrtf(np) * TEMP_INV;

        float mx = pos;
        float lg[5];
        const float* ng = negs + (size_t)e * 320;
        #pragma unroll
        for (int m = 0; m < 5; ++m) {
            float n0 = ng[m * 64 + lane], n1 = ng[m * 64 + 32 + lane];
            float dn = warp_sum(o0 * n0 + o1 * n1);
            float nn = warp_sum(n0 * n0 + n1 * n1);
            lg[m] = dn * rq * rsqrtf(nn) * TEMP_INV;
            mx = fmaxf(mx, lg[m]);
        }
        float s = expf(pos - mx);
        #pragma unroll
        for (int m = 0; m < 5; ++m) s += expf(lg[m] - mx);
        lsum += mx + logf(s) - pos;   // identical on every lane
    }

    if (lane == 0) wSums[wid] = lsum;
    __syncthreads();
    if (tid == 0) {
        float bs = 0.f;
        #pragma unroll
        for (int w = 0; w < 8; ++w) bs += wSums[w];
        g_partials[blockIdx.x] = bs;   // deterministic: fixed slot, no atomics
    }
}

// ---------------- finalize: deterministic reduction ----------------
__global__ void finalize_kernel(float* out, int nblk, int E) {
    __shared__ float sh[256];
    float s = 0.f;
    for (int i = threadIdx.x; i < nblk; i += 256) s += g_partials[i];
    sh[threadIdx.x] = s;
    __syncthreads();
    for (int st = 128; st > 0; st >>= 1) {
        if (threadIdx.x < st) sh[threadIdx.x] += sh[threadIdx.x + st];
        __syncthreads();
    }
    if (threadIdx.x == 0) out[0] = sh[0] / (float)E;
}

// ---------------- launch ----------------
extern "C" void kernel_launch(void* const* d_in, const int* in_sizes, int n_in,
                              void* d_out, int out_size) {
    const float* ufeat  = (const float*)d_in[0];
    const float* ifeat  = (const float*)d_in[1];
    const float* review = (const float*)d_in[2];
    const float* negs   = (const float*)d_in[3];
    const float* W1     = (const float*)d_in[4];
    const float* W2     = (const float*)d_in[5];
    const int*   src    = (const int*)d_in[6];
    const int*   dst    = (const int*)d_in[7];
    (void)n_in; (void)out_size;

    int E = in_sizes[6];                       // src_idx element count
    int nblk = (E + TILE_M - 1) / TILE_M;      // 3907 for E=500000

    cudaFuncSetAttribute(fused_kernel,
                         cudaFuncAttributeMaxDynamicSharedMemorySize, SMEM_TOTAL);

    fused_kernel<<<nblk, 256, SMEM_TOTAL>>>(ufeat, ifeat, review, negs,
                                            W1, W2, src, dst, E);
    finalize_kernel<<<1, 256>>>((float*)d_out, nblk, E);
}

// round 2
// speedup vs baseline: 1.1926x; 1.1926x over previous
#include <cuda_runtime.h>
#include <cuda_bf16.h>
#include <cstdint>

// ---------------- constants ----------------
#define TEMP_INV 10.0f
#define TILE_M   128

// smem layout (bytes)
#define OFF_WB0  65536            // sA swizzled: 128 rows * 512B
#define OFF_WB1  81920            // + 16384
#define OFF_W2   98304            // + 16384
#define OFF_IDX  114688           // + 16384
#define SMEM_TOTAL 115712         // + 1024 (idx). 2*(115712+1024)=233472=228KB exact

// H tile (overwrites sA zone after GEMM1)
#define PH  136
// OUT tile fp32 (overwrites zone0 after GEMM2)
#define PO  68
#define OFF_WSUM 35840            // inside zone0, after OUT (128*68*4=34816)

__device__ float g_partials[8192];
__device__ __nv_bfloat16 g_w1[256 * 128];
__device__ __nv_bfloat16 g_w2[128 * 64];

// ---------------- PTX helpers ----------------
__device__ __forceinline__ uint32_t sptr(const void* p) {
    return (uint32_t)__cvta_generic_to_shared(p);
}
__device__ __forceinline__ void ldm_x4(uint32_t a, uint32_t& r0, uint32_t& r1,
                                       uint32_t& r2, uint32_t& r3) {
    asm volatile("ldmatrix.sync.aligned.m8n8.x4.shared.b16 {%0,%1,%2,%3}, [%4];"
                 : "=r"(r0), "=r"(r1), "=r"(r2), "=r"(r3) : "r"(a));
}
__device__ __forceinline__ void ldm_x4_t(uint32_t a, uint32_t& r0, uint32_t& r1,
                                         uint32_t& r2, uint32_t& r3) {
    asm volatile("ldmatrix.sync.aligned.m8n8.x4.trans.shared.b16 {%0,%1,%2,%3}, [%4];"
                 : "=r"(r0), "=r"(r1), "=r"(r2), "=r"(r3) : "r"(a));
}
__device__ __forceinline__ void mma16816(float* d, const uint32_t* a,
                                         uint32_t b0, uint32_t b1) {
    asm volatile(
        "mma.sync.aligned.m16n8k16.row.col.f32.bf16.bf16.f32 "
        "{%0,%1,%2,%3}, {%4,%5,%6,%7}, {%8,%9}, {%0,%1,%2,%3};"
        : "+f"(d[0]), "+f"(d[1]), "+f"(d[2]), "+f"(d[3])
        : "r"(a[0]), "r"(a[1]), "r"(a[2]), "r"(a[3]), "r"(b0), "r"(b1));
}
__device__ __forceinline__ void cpa16(uint32_t dst, const void* src) {
    asm volatile("cp.async.ca.shared.global [%0], [%1], 16;"
                 :: "r"(dst), "l"(src) : "memory");
}
__device__ __forceinline__ void cp_commit() {
    asm volatile("cp.async.commit_group;" ::: "memory");
}
template <int N> __device__ __forceinline__ void cp_wait() {
    asm volatile("cp.async.wait_group %0;" :: "n"(N) : "memory");
}

// copy one W1 K-chunk (64 rows x 128 bf16) into a swizzled smem buffer
__device__ __forceinline__ void copy_w1_chunk(int kc, uint32_t buf_su, int tid) {
    #pragma unroll
    for (int i = tid; i < 1024; i += 256) {          // 64 rows * 16 units
        int r = i >> 4, u = i & 15;
        cpa16(buf_su + r * 256 + ((u ^ (r & 7)) << 4),
              g_w1 + (size_t)(kc * 64 + r) * 128 + u * 8);
    }
}
__device__ __forceinline__ void copy_w2(uint32_t w2_su, int tid) {
    #pragma unroll
    for (int i = tid; i < 1024; i += 256) {          // 128 rows * 8 units
        int r = i >> 3, u = i & 7;
        cpa16(w2_su + r * 128 + ((u ^ (r & 7)) << 4),
              g_w2 + (size_t)r * 64 + u * 8);
    }
}

// MMA over one K=64 chunk of GEMM1
__device__ __forceinline__ void mma_chunk(int kc, uint32_t sA_su, uint32_t buf_su,
                                          float acc[2][8][4], int wm, int wn, int lane) {
    #pragma unroll
    for (int ks = 0; ks < 4; ++ks) {
        const int kg = kc * 64 + ks * 16;
        const int u = (kg >> 3) + (lane >> 4);
        uint32_t a0[4], a1[4];
        {
            int r = wm + (lane & 15);
            ldm_x4(sA_su + r * 512 + ((u ^ (r & 7)) << 4), a0[0], a0[1], a0[2], a0[3]);
            r += 16;
            ldm_x4(sA_su + r * 512 + ((u ^ (r & 7)) << 4), a1[0], a1[1], a1[2], a1[3]);
        }
        const int lr = ks * 16 + (lane & 15);
        #pragma unroll
        for (int nb = 0; nb < 4; ++nb) {
            int cu = (wn >> 3) + nb * 2 + (lane >> 4);
            uint32_t b0, b1, b2, b3;
            ldm_x4_t(buf_su + lr * 256 + ((cu ^ (lr & 7)) << 4), b0, b1, b2, b3);
            mma16816(acc[0][2 * nb],     a0, b0, b1);
            mma16816(acc[0][2 * nb + 1], a0, b2, b3);
            mma16816(acc[1][2 * nb],     a1, b0, b1);
            mma16816(acc[1][2 * nb + 1], a1, b2, b3);
        }
    }
}

// ---------------- fused kernel ----------------
__global__ void __launch_bounds__(256, 2) fused_kernel(
    const float* __restrict__ ufeat, const float* __restrict__ ifeat,
    const float* __restrict__ review, const float* __restrict__ negs,
    const int* __restrict__ src, const int* __restrict__ dst, int E)
{
    extern __shared__ char smem[];
    const uint32_t sA_su  = sptr(smem);
    const uint32_t wb0_su = sA_su + OFF_WB0;
    const uint32_t wb1_su = sA_su + OFF_WB1;
    const uint32_t w2_su  = sA_su + OFF_W2;
    int* sSrc = (int*)(smem + OFF_IDX);
    int* sDst = sSrc + 128;
    float* wSums = (float*)(smem + OFF_WSUM);

    const int tid = threadIdx.x;
    const int lane = tid & 31;
    const int wid = tid >> 5;
    const int base = blockIdx.x * TILE_M;

    // ---- issue weight copies first (overlap with gather) ----
    copy_w1_chunk(0, wb0_su, tid); cp_commit();      // g: c0
    copy_w1_chunk(1, wb1_su, tid); cp_commit();      // g: c1
    copy_w2(w2_su, tid);           cp_commit();      // g: W2

    // ---- indices ----
    if (tid < 128) {
        int e = base + tid;
        sSrc[tid] = (e < E) ? src[e] : src[0];
    } else {
        int t = tid - 128;
        int e = base + t;
        sDst[t] = (e < E) ? dst[e] : dst[0];
    }
    __syncthreads();

    // ---- gather A tile: 128 rows x 256 bf16, 16B-unit XOR swizzle ----
    #pragma unroll 4
    for (int i = tid; i < 128 * 32; i += 256) {
        int r = i >> 5, u = i & 31;
        int c = u * 8;                               // source float col in [0,256)
        const float* p = (c < 128) ? (ufeat + (size_t)sSrc[r] * 128 + c)
                                   : (ifeat + (size_t)sDst[r] * 128 + (c - 128));
        float4 v0 = *(const float4*)p;
        float4 v1 = *(const float4*)(p + 4);
        uint32_t w[4];
        *(__nv_bfloat162*)&w[0] = __floats2bfloat162_rn(v0.x, v0.y);
        *(__nv_bfloat162*)&w[1] = __floats2bfloat162_rn(v0.z, v0.w);
        *(__nv_bfloat162*)&w[2] = __floats2bfloat162_rn(v1.x, v1.y);
        *(__nv_bfloat162*)&w[3] = __floats2bfloat162_rn(v1.z, v1.w);
        uint32_t dst_su = sA_su + r * 512 + ((u ^ (r & 7)) << 4);
        asm volatile("st.shared.v4.b32 [%0], {%1,%2,%3,%4};"
                     :: "r"(dst_su), "r"(w[0]), "r"(w[1]), "r"(w[2]), "r"(w[3]));
    }

    // ---- GEMM1: C[128,128] = A @ W1, double-buffered K=64 chunks ----
    float acc[2][8][4];
    #pragma unroll
    for (int a = 0; a < 2; ++a)
        #pragma unroll
        for (int b = 0; b < 8; ++b)
            #pragma unroll
            for (int c = 0; c < 4; ++c) acc[a][b][c] = 0.f;

    const int wm = (wid & 3) * 32;
    const int wn = (wid >> 2) * 64;

    cp_wait<2>(); __syncthreads();                   // c0 ready (+gather visible)
    mma_chunk(0, sA_su, wb0_su, acc, wm, wn, lane);
    __syncthreads();                                 // buf0 reads done
    copy_w1_chunk(2, wb0_su, tid); cp_commit();      // g: c2

    cp_wait<2>(); __syncthreads();                   // c1 ready
    mma_chunk(1, sA_su, wb1_su, acc, wm, wn, lane);
    __syncthreads();                                 // buf1 reads done
    copy_w1_chunk(3, wb1_su, tid); cp_commit();      // g: c3

    cp_wait<1>(); __syncthreads();                   // c2 (and W2) ready
    mma_chunk(2, sA_su, wb0_su, acc, wm, wn, lane);

    cp_wait<0>(); __syncthreads();                   // c3 ready
    mma_chunk(3, sA_su, wb1_su, acc, wm, wn, lane);
    __syncthreads();                                 // all sA reads done

    // ---- relu + H (bf16, padded pitch, overwrites sA zone) ----
    __nv_bfloat16* sH = (__nv_bfloat16*)smem;
    #pragma unroll
    for (int mi = 0; mi < 2; ++mi)
        #pragma unroll
        for (int nj = 0; nj < 8; ++nj) {
            int row = wm + mi * 16 + (lane >> 2);
            int col = wn + nj * 8 + (lane & 3) * 2;
            float* c = acc[mi][nj];
            *(__nv_bfloat162*)&sH[row * PH + col] =
                __floats2bfloat162_rn(fmaxf(c[0], 0.f), fmaxf(c[1], 0.f));
            *(__nv_bfloat162*)&sH[(row + 8) * PH + col] =
                __floats2bfloat162_rn(fmaxf(c[2], 0.f), fmaxf(c[3], 0.f));
        }
    __syncthreads();

    // ---- GEMM2: OUT[128,64] = H @ W2 (W2 swizzled in smem) ----
    float acc2[8][4];
    #pragma unroll
    for (int b = 0; b < 8; ++b)
        #pragma unroll
        for (int c = 0; c < 4; ++c) acc2[b][c] = 0.f;

    const int m0 = wid * 16;
    #pragma unroll
    for (int k = 0; k < 8; ++k) {
        int kg = k * 16;
        uint32_t a[4];
        ldm_x4(sptr(&sH[(m0 + (lane & 15)) * PH + kg + ((lane >> 4) << 3)]),
               a[0], a[1], a[2], a[3]);
        const int lr = kg + (lane & 15);
        #pragma unroll
        for (int nb = 0; nb < 4; ++nb) {
            int cu = nb * 2 + (lane >> 4);
            uint32_t b0, b1, b2, b3;
            ldm_x4_t(w2_su + lr * 128 + ((cu ^ (lr & 7)) << 4), b0, b1, b2, b3);
            mma16816(acc2[2 * nb],     a, b0, b1);
            mma16816(acc2[2 * nb + 1], a, b2, b3);
        }
    }
    __syncthreads();                                 // H reads done

    float* sOUT = (float*)smem;
    #pragma unroll
    for (int nj = 0; nj < 8; ++nj) {
        int row = m0 + (lane >> 2);
        int col = nj * 8 + (lane & 3) * 2;
        *(float2*)&sOUT[row * PO + col]       = make_float2(acc2[nj][0], acc2[nj][1]);
        *(float2*)&sOUT[(row + 8) * PO + col] = make_float2(acc2[nj][2], acc2[nj][3]);
    }
    __syncthreads();

    // ---- epilogue: paired InfoNCE, ONE batched butterfly per edge ----
    float lsum = 0.f;
    for (int rr = 0; rr < 16; ++rr) {
        int r = m0 + rr;
        int e = base + r;
        if (e >= E) continue;

        float o0 = sOUT[r * PO + lane];
        float o1 = sOUT[r * PO + 32 + lane];
        const float* pr = review + (size_t)e * 64;
        float p0 = pr[lane], p1 = pr[lane + 32];
        const float* ng = negs + (size_t)e * 320;

        float v[13];
        v[0] = o0 * o0 + o1 * o1;
        v[1] = o0 * p0 + o1 * p1;
        v[2] = p0 * p0 + p1 * p1;
        #pragma unroll
        for (int m = 0; m < 5; ++m) {
            float n0 = ng[m * 64 + lane], n1 = ng[m * 64 + 32 + lane];
            v[3 + 2 * m] = o0 * n0 + o1 * n1;
            v[4 + 2 * m] = n0 * n0 + n1 * n1;
        }
        #pragma unroll
        for (int off = 16; off > 0; off >>= 1)
            #pragma unroll
            for (int j = 0; j < 13; ++j)
                v[j] += __shfl_xor_sync(0xffffffffu, v[j], off);

        float rq = rsqrtf(v[0]);
        float pos = v[1] * rq * rsqrtf(v[2]) * TEMP_INV;
        float mx = pos;
        float lg[5];
        #pragma unroll
        for (int m = 0; m < 5; ++m) {
            lg[m] = v[3 + 2 * m] * rq * rsqrtf(v[4 + 2 * m]) * TEMP_INV;
            mx = fmaxf(mx, lg[m]);
        }
        float s = __expf(pos - mx);
        #pragma unroll
        for (int m = 0; m < 5; ++m) s += __expf(lg[m] - mx);
        lsum += mx + __logf(s) - pos;
    }

    if (lane == 0) wSums[wid] = lsum;
    __syncthreads();
    if (tid == 0) {
        float bs = 0.f;
        #pragma unroll
        for (int w = 0; w < 8; ++w) bs += wSums[w];
        g_partials[blockIdx.x] = bs;
    }
}

// ---------------- weight pre-conversion ----------------
__global__ void cvt_kernel(const float* __restrict__ W1, const float* __restrict__ W2) {
    int i = blockIdx.x * 256 + threadIdx.x;
    if (i < 256 * 128) g_w1[i] = __float2bfloat16(W1[i]);
    if (i < 128 * 64)  g_w2[i] = __float2bfloat16(W2[i]);
}

// ---------------- finalize ----------------
__global__ void finalize_kernel(float* out, int nblk, int E) {
    __shared__ float sh[256];
    float s = 0.f;
    for (int i = threadIdx.x; i < nblk; i += 256) s += g_partials[i];
    sh[threadIdx.x] = s;
    __syncthreads();
    for (int st = 128; st > 0; st >>= 1) {
        if (threadIdx.x < st) sh[threadIdx.x] += sh[threadIdx.x + st];
        __syncthreads();
    }
    if (threadIdx.x == 0) out[0] = sh[0] / (float)E;
}

// ---------------- launch ----------------
extern "C" void kernel_launch(void* const* d_in, const int* in_sizes, int n_in,
                              void* d_out, int out_size) {
    const float* ufeat  = (const float*)d_in[0];
    const float* ifeat  = (const float*)d_in[1];
    const float* review = (const float*)d_in[2];
    const float* negs   = (const float*)d_in[3];
    const float* W1     = (const float*)d_in[4];
    const float* W2     = (const float*)d_in[5];
    const int*   src    = (const int*)d_in[6];
    const int*   dst    = (const int*)d_in[7];
    (void)n_in; (void)out_size;

    int E = in_sizes[6];
    int nblk = (E + TILE_M - 1) / TILE_M;

    cvt_kernel<<<128, 256>>>(W1, W2);

    cudaFuncSetAttribute(fused_kernel,
                         cudaFuncAttributeMaxDynamicSharedMemorySize, SMEM_TOTAL);
    fused_kernel<<<nblk, 256, SMEM_TOTAL>>>(ufeat, ifeat, review, negs,
                                            src, dst, E);
    finalize_kernel<<<1, 256>>>((float*)d_out, nblk, E);
}

// round 3
// speedup vs baseline: 1.3150x; 1.1026x over previous
#include <cuda_runtime.h>
#include <cuda_bf16.h>
#include <cstdint>

// ---------------- constants ----------------
#define TEMP_INV 10.0f
#define TILE_M   128

// smem layout (bytes)
#define OFF_WB0  65536            // sA swizzled: 128 rows * 512B
#define OFF_WB1  81920            // + 16384
#define OFF_W2   98304            // + 16384
#define OFF_IDX  114688           // + 16384
#define SMEM_TOTAL 115712         // + 1024 (idx)

#define PH  136                   // H tile pitch (bf16)
#define PO  68                    // OUT tile pitch (fp32)
#define OFF_WSUM 35840            // after OUT (128*68*4=34816) in zone0

__device__ float g_partials[8192];
__device__ __nv_bfloat16 g_w1[256 * 128];
__device__ __nv_bfloat16 g_w2[128 * 64];

// ---------------- PTX helpers ----------------
__device__ __forceinline__ uint32_t sptr(const void* p) {
    return (uint32_t)__cvta_generic_to_shared(p);
}
__device__ __forceinline__ void ldm_x4(uint32_t a, uint32_t& r0, uint32_t& r1,
                                       uint32_t& r2, uint32_t& r3) {
    asm volatile("ldmatrix.sync.aligned.m8n8.x4.shared.b16 {%0,%1,%2,%3}, [%4];"
                 : "=r"(r0), "=r"(r1), "=r"(r2), "=r"(r3) : "r"(a));
}
__device__ __forceinline__ void ldm_x4_t(uint32_t a, uint32_t& r0, uint32_t& r1,
                                         uint32_t& r2, uint32_t& r3) {
    asm volatile("ldmatrix.sync.aligned.m8n8.x4.trans.shared.b16 {%0,%1,%2,%3}, [%4];"
                 : "=r"(r0), "=r"(r1), "=r"(r2), "=r"(r3) : "r"(a));
}
__device__ __forceinline__ void mma16816(float* d, const uint32_t* a,
                                         uint32_t b0, uint32_t b1) {
    asm volatile(
        "mma.sync.aligned.m16n8k16.row.col.f32.bf16.bf16.f32 "
        "{%0,%1,%2,%3}, {%4,%5,%6,%7}, {%8,%9}, {%0,%1,%2,%3};"
        : "+f"(d[0]), "+f"(d[1]), "+f"(d[2]), "+f"(d[3])
        : "r"(a[0]), "r"(a[1]), "r"(a[2]), "r"(a[3]), "r"(b0), "r"(b1));
}
__device__ __forceinline__ void cpa16(uint32_t dst, const void* src) {
    asm volatile("cp.async.ca.shared.global [%0], [%1], 16;"
                 :: "r"(dst), "l"(src) : "memory");
}
__device__ __forceinline__ void cp_commit() {
    asm volatile("cp.async.commit_group;" ::: "memory");
}
template <int N> __device__ __forceinline__ void cp_wait() {
    asm volatile("cp.async.wait_group %0;" :: "n"(N) : "memory");
}

__device__ __forceinline__ void copy_w1_chunk(int kc, uint32_t buf_su, int tid) {
    #pragma unroll
    for (int i = tid; i < 1024; i += 256) {
        int r = i >> 4, u = i & 15;
        cpa16(buf_su + r * 256 + ((u ^ (r & 7)) << 4),
              g_w1 + (size_t)(kc * 64 + r) * 128 + u * 8);
    }
}
__device__ __forceinline__ void copy_w2(uint32_t w2_su, int tid) {
    #pragma unroll
    for (int i = tid; i < 1024; i += 256) {
        int r = i >> 3, u = i & 7;
        cpa16(w2_su + r * 128 + ((u ^ (r & 7)) << 4),
              g_w2 + (size_t)r * 64 + u * 8);
    }
}

__device__ __forceinline__ void mma_chunk(int kc, uint32_t sA_su, uint32_t buf_su,
                                          float acc[2][8][4], int wm, int wn, int lane) {
    #pragma unroll
    for (int ks = 0; ks < 4; ++ks) {
        const int kg = kc * 64 + ks * 16;
        const int u = (kg >> 3) + (lane >> 4);
        uint32_t a0[4], a1[4];
        {
            int r = wm + (lane & 15);
            ldm_x4(sA_su + r * 512 + ((u ^ (r & 7)) << 4), a0[0], a0[1], a0[2], a0[3]);
            r += 16;
            ldm_x4(sA_su + r * 512 + ((u ^ (r & 7)) << 4), a1[0], a1[1], a1[2], a1[3]);
        }
        const int lr = ks * 16 + (lane & 15);
        #pragma unroll
        for (int nb = 0; nb < 4; ++nb) {
            int cu = (wn >> 3) + nb * 2 + (lane >> 4);
            uint32_t b0, b1, b2, b3;
            ldm_x4_t(buf_su + lr * 256 + ((cu ^ (lr & 7)) << 4), b0, b1, b2, b3);
            mma16816(acc[0][2 * nb],     a0, b0, b1);
            mma16816(acc[0][2 * nb + 1], a0, b2, b3);
            mma16816(acc[1][2 * nb],     a1, b0, b1);
            mma16816(acc[1][2 * nb + 1], a1, b2, b3);
        }
    }
}

// ---------------- fused kernel ----------------
__global__ void __launch_bounds__(256, 2) fused_kernel(
    const float* __restrict__ ufeat, const float* __restrict__ ifeat,
    const float* __restrict__ review, const float* __restrict__ negs,
    const int* __restrict__ src, const int* __restrict__ dst, int E)
{
    extern __shared__ char smem[];
    const uint32_t sA_su  = sptr(smem);
    const uint32_t wb0_su = sA_su + OFF_WB0;
    const uint32_t wb1_su = sA_su + OFF_WB1;
    const uint32_t w2_su  = sA_su + OFF_W2;
    int* sSrc = (int*)(smem + OFF_IDX);
    int* sDst = sSrc + 128;
    float* wSums = (float*)(smem + OFF_WSUM);

    const int tid = threadIdx.x;
    const int lane = tid & 31;
    const int wid = tid >> 5;
    const int base = blockIdx.x * TILE_M;

    // ---- issue weight copies (overlap with gather) ----
    copy_w1_chunk(0, wb0_su, tid); cp_commit();
    copy_w1_chunk(1, wb1_su, tid); cp_commit();
    copy_w2(w2_su, tid);           cp_commit();

    // ---- indices ----
    if (tid < 128) {
        int e = base + tid;
        sSrc[tid] = (e < E) ? src[e] : src[0];
    } else {
        int t = tid - 128;
        int e = base + t;
        sDst[t] = (e < E) ? dst[e] : dst[0];
    }
    __syncthreads();

    // ---- gather A tile: 128 x 256 bf16, XOR-swizzled ----
    #pragma unroll 4
    for (int i = tid; i < 128 * 32; i += 256) {
        int r = i >> 5, u = i & 31;
        int c = u * 8;
        const float* p = (c < 128) ? (ufeat + (size_t)sSrc[r] * 128 + c)
                                   : (ifeat + (size_t)sDst[r] * 128 + (c - 128));
        float4 v0 = *(const float4*)p;
        float4 v1 = *(const float4*)(p + 4);
        uint32_t w[4];
        *(__nv_bfloat162*)&w[0] = __floats2bfloat162_rn(v0.x, v0.y);
        *(__nv_bfloat162*)&w[1] = __floats2bfloat162_rn(v0.z, v0.w);
        *(__nv_bfloat162*)&w[2] = __floats2bfloat162_rn(v1.x, v1.y);
        *(__nv_bfloat162*)&w[3] = __floats2bfloat162_rn(v1.z, v1.w);
        uint32_t dst_su = sA_su + r * 512 + ((u ^ (r & 7)) << 4);
        asm volatile("st.shared.v4.b32 [%0], {%1,%2,%3,%4};"
                     :: "r"(dst_su), "r"(w[0]), "r"(w[1]), "r"(w[2]), "r"(w[3]));
    }

    // ---- GEMM1 (double-buffered K=64 chunks) ----
    float acc[2][8][4];
    #pragma unroll
    for (int a = 0; a < 2; ++a)
        #pragma unroll
        for (int b = 0; b < 8; ++b)
            #pragma unroll
            for (int c = 0; c < 4; ++c) acc[a][b][c] = 0.f;

    const int wm = (wid & 3) * 32;
    const int wn = (wid >> 2) * 64;

    cp_wait<2>(); __syncthreads();
    mma_chunk(0, sA_su, wb0_su, acc, wm, wn, lane);
    __syncthreads();
    copy_w1_chunk(2, wb0_su, tid); cp_commit();

    cp_wait<2>(); __syncthreads();
    mma_chunk(1, sA_su, wb1_su, acc, wm, wn, lane);
    __syncthreads();
    copy_w1_chunk(3, wb1_su, tid); cp_commit();

    cp_wait<1>(); __syncthreads();
    mma_chunk(2, sA_su, wb0_su, acc, wm, wn, lane);

    cp_wait<0>(); __syncthreads();
    mma_chunk(3, sA_su, wb1_su, acc, wm, wn, lane);
    __syncthreads();

    // ---- relu + H (bf16, overwrites sA zone) ----
    __nv_bfloat16* sH = (__nv_bfloat16*)smem;
    #pragma unroll
    for (int mi = 0; mi < 2; ++mi)
        #pragma unroll
        for (int nj = 0; nj < 8; ++nj) {
            int row = wm + mi * 16 + (lane >> 2);
            int col = wn + nj * 8 + (lane & 3) * 2;
            float* c = acc[mi][nj];
            *(__nv_bfloat162*)&sH[row * PH + col] =
                __floats2bfloat162_rn(fmaxf(c[0], 0.f), fmaxf(c[1], 0.f));
            *(__nv_bfloat162*)&sH[(row + 8) * PH + col] =
                __floats2bfloat162_rn(fmaxf(c[2], 0.f), fmaxf(c[3], 0.f));
        }
    __syncthreads();

    // ---- GEMM2: OUT[128,64] = H @ W2 ----
    float acc2[8][4];
    #pragma unroll
    for (int b = 0; b < 8; ++b)
        #pragma unroll
        for (int c = 0; c < 4; ++c) acc2[b][c] = 0.f;

    const int m0 = wid * 16;
    #pragma unroll
    for (int k = 0; k < 8; ++k) {
        int kg = k * 16;
        uint32_t a[4];
        ldm_x4(sptr(&sH[(m0 + (lane & 15)) * PH + kg + ((lane >> 4) << 3)]),
               a[0], a[1], a[2], a[3]);
        const int lr = kg + (lane & 15);
        #pragma unroll
        for (int nb = 0; nb < 4; ++nb) {
            int cu = nb * 2 + (lane >> 4);
            uint32_t b0, b1, b2, b3;
            ldm_x4_t(w2_su + lr * 128 + ((cu ^ (lr & 7)) << 4), b0, b1, b2, b3);
            mma16816(acc2[2 * nb],     a, b0, b1);
            mma16816(acc2[2 * nb + 1], a, b2, b3);
        }
    }
    __syncthreads();

    float* sOUT = (float*)smem;
    #pragma unroll
    for (int nj = 0; nj < 8; ++nj) {
        int row = m0 + (lane >> 2);
        int col = nj * 8 + (lane & 3) * 2;
        *(float2*)&sOUT[row * PO + col]       = make_float2(acc2[nj][0], acc2[nj][1]);
        *(float2*)&sOUT[(row + 8) * PO + col] = make_float2(acc2[nj][2], acc2[nj][3]);
    }
    __syncthreads();

    // ---- epilogue: paired InfoNCE, pair-pipelined, float2 loads ----
    // Lane covers elems [2*lane, 2*lane+1] of each 64-dim vector; butterfly
    // sums over all lanes so the element->lane mapping is irrelevant.
    float lsum = 0.f;
    float2 P[2], O[2], N[2][5];

    // load helper (clamped to edge 0 when out of range; contribution dropped)
    auto load_edge = [&](int b, int rr) {
        int r = m0 + rr;
        long e = base + r;
        long ec = (e < E) ? e : 0;
        const float* pr = review + ec * 64;
        const float* ng = negs + ec * 320;
        P[b] = *(const float2*)(pr + 2 * lane);
        #pragma unroll
        for (int m = 0; m < 5; ++m)
            N[b][m] = *(const float2*)(ng + m * 64 + 2 * lane);
        O[b] = *(const float2*)&sOUT[r * PO + 2 * lane];
    };

    load_edge(0, 0);
    load_edge(1, 1);

    for (int pp = 0; pp < 8; ++pp) {
        // per-lane partials for both edges of the pair
        float v[26];
        #pragma unroll
        for (int b = 0; b < 2; ++b) {
            float ox = O[b].x, oy = O[b].y;
            v[13 * b + 0] = ox * ox + oy * oy;
            v[13 * b + 1] = ox * P[b].x + oy * P[b].y;
            v[13 * b + 2] = P[b].x * P[b].x + P[b].y * P[b].y;
            #pragma unroll
            for (int m = 0; m < 5; ++m) {
                float nx = N[b][m].x, ny = N[b][m].y;
                v[13 * b + 3 + 2 * m] = ox * nx + oy * ny;
                v[13 * b + 4 + 2 * m] = nx * nx + ny * ny;
            }
        }

        // prefetch next pair while the butterfly runs
        if (pp < 7) {
            load_edge(0, 2 * pp + 2);
            load_edge(1, 2 * pp + 3);
        }

        #pragma unroll
        for (int off = 16; off > 0; off >>= 1)
            #pragma unroll
            for (int j = 0; j < 26; ++j)
                v[j] += __shfl_xor_sync(0xffffffffu, v[j], off);

        #pragma unroll
        for (int b = 0; b < 2; ++b) {
            int e = base + m0 + 2 * pp + b;
            float rq = rsqrtf(v[13 * b + 0]);
            float pos = v[13 * b + 1] * rq * rsqrtf(v[13 * b + 2]) * TEMP_INV;
            float mx = pos;
            float lg[5];
            #pragma unroll
            for (int m = 0; m < 5; ++m) {
                lg[m] = v[13 * b + 3 + 2 * m] * rq *
                        rsqrtf(v[13 * b + 4 + 2 * m]) * TEMP_INV;
                mx = fmaxf(mx, lg[m]);
            }
            float s = __expf(pos - mx);
            #pragma unroll
            for (int m = 0; m < 5; ++m) s += __expf(lg[m] - mx);
            if (e < E) lsum += mx + __logf(s) - pos;
        }
    }

    if (lane == 0) wSums[wid] = lsum;
    __syncthreads();
    if (tid == 0) {
        float bs = 0.f;
        #pragma unroll
        for (int w = 0; w < 8; ++w) bs += wSums[w];
        g_partials[blockIdx.x] = bs;
    }
}

// ---------------- weight pre-conversion ----------------
__global__ void cvt_kernel(const float* __restrict__ W1, const float* __restrict__ W2) {
    int i = blockIdx.x * 256 + threadIdx.x;
    if (i < 256 * 128) g_w1[i] = __float2bfloat16(W1[i]);
    if (i < 128 * 64)  g_w2[i] = __float2bfloat16(W2[i]);
}

// ---------------- finalize ----------------
__global__ void finalize_kernel(float* out, int nblk, int E) {
    __shared__ float sh[256];
    float s = 0.f;
    for (int i = threadIdx.x; i < nblk; i += 256) s += g_partials[i];
    sh[threadIdx.x] = s;
    __syncthreads();
    for (int st = 128; st > 0; st >>= 1) {
        if (threadIdx.x < st) sh[threadIdx.x] += sh[threadIdx.x + st];
        __syncthreads();
    }
    if (threadIdx.x == 0) out[0] = sh[0] / (float)E;
}

// ---------------- launch ----------------
extern "C" void kernel_launch(void* const* d_in, const int* in_sizes, int n_in,
                              void* d_out, int out_size) {
    const float* ufeat  = (const float*)d_in[0];
    const float* ifeat  = (const float*)d_in[1];
    const float* review = (const float*)d_in[2];
    const float* negs   = (const float*)d_in[3];
    const float* W1     = (const float*)d_in[4];
    const float* W2     = (const float*)d_in[5];
    const int*   src    = (const int*)d_in[6];
    const int*   dst    = (const int*)d_in[7];
    (void)n_in; (void)out_size;

    int E = in_sizes[6];
    int nblk = (E + TILE_M - 1) / TILE_M;

    cvt_kernel<<<128, 256>>>(W1, W2);

    cudaFuncSetAttribute(fused_kernel,
                         cudaFuncAttributeMaxDynamicSharedMemorySize, SMEM_TOTAL);
    fused_kernel<<<nblk, 256, SMEM_TOTAL>>>(ufeat, ifeat, review, negs,
                                            src, dst, E);
    finalize_kernel<<<1, 256>>>((float*)d_out, nblk, E);
}